// round 6
// baseline (speedup 1.0000x reference)
#include <cuda_runtime.h>
#include <math.h>
#include <stdint.h>

#define BATCH 4
#define SEQ   4096
#define DIM   256
#define TOPK  32
#define ROWS  (BATCH*SEQ)

#define TQ     128
#define TK     128
#define BK     8
#define SSTR   132   // score stage stride (floats): conflict-free float4 row scans
#define CHUNKS 4
#define CKEYS  (SEQ/CHUNKS)   // 1024 keys per chunk CTA

// ---------------- device scratch (allocation-free contract) ----------------
__device__ float g_q[ROWS*DIM];
__device__ float g_k[ROWS*DIM];
__device__ float g_v[ROWS*DIM];
// partial top-k lists: [bq(128)][chunk(4)][j(32)][q(128)]
__device__ float g_pv[128*CHUNKS*TOPK*128];
__device__ int   g_pi[128*CHUNKS*TOPK*128];

// ---------------------------------------------------------------------------
// Kernel 1: fused QKV projection, double-buffered pipeline.
// ---------------------------------------------------------------------------
__global__ __launch_bounds__(256, 2)
void qkv_kernel(const float* __restrict__ x,
                const float* __restrict__ Wq, const float* __restrict__ bq,
                const float* __restrict__ Wk, const float* __restrict__ bk,
                const float* __restrict__ Wv, const float* __restrict__ bv)
{
    __shared__ float As[2][BK*128];
    __shared__ float Bs[2][BK*128];

    const int which = blockIdx.z;
    const float* W    = (which==0) ? Wq : (which==1) ? Wk : Wv;
    const float* bias = (which==0) ? bq : (which==1) ? bk : bv;
    float* outp       = (which==0) ? g_q : (which==1) ? g_k : g_v;

    const int tid = threadIdx.x;
    const int tx = tid & 15, ty = tid >> 4;
    const int row0 = blockIdx.x * 128;
    const int col0 = blockIdx.y * 128;

    float acc[8][8];
    #pragma unroll
    for (int i = 0; i < 8; i++)
        #pragma unroll
        for (int j = 0; j < 8; j++) acc[i][j] = 0.f;

    const int amm = tid >> 1;
    const int akk = (tid & 1) * 4;
    const int bkk = tid >> 5;
    const int bnn = (tid & 31) * 4;

    const int NST = DIM / BK;   // 32 stages
    float4 rA, rB;

    // prologue: stage 0
    rA = *(const float4*)&x[(size_t)(row0 + amm)*DIM + akk];
    rB = *(const float4*)&W[(size_t)bkk*DIM + col0 + bnn];
    As[0][(akk+0)*128 + amm] = rA.x;
    As[0][(akk+1)*128 + amm] = rA.y;
    As[0][(akk+2)*128 + amm] = rA.z;
    As[0][(akk+3)*128 + amm] = rA.w;
    *(float4*)&Bs[0][bkk*128 + bnn] = rB;
    __syncthreads();

    for (int s = 0; s < NST; s++) {
        if (s + 1 < NST) {
            const int k0 = (s+1) * BK;
            rA = *(const float4*)&x[(size_t)(row0 + amm)*DIM + k0 + akk];
            rB = *(const float4*)&W[(size_t)(k0 + bkk)*DIM + col0 + bnn];
        }
        const float* Ac = As[s & 1];
        const float* Bc = Bs[s & 1];
        #pragma unroll
        for (int kk = 0; kk < BK; kk++) {
            float a[8], b[8];
            *(float4*)&a[0] = *(const float4*)&Ac[kk*128 + ty*8];
            *(float4*)&a[4] = *(const float4*)&Ac[kk*128 + ty*8 + 4];
            *(float4*)&b[0] = *(const float4*)&Bc[kk*128 + tx*8];
            *(float4*)&b[4] = *(const float4*)&Bc[kk*128 + tx*8 + 4];
            #pragma unroll
            for (int i = 0; i < 8; i++)
                #pragma unroll
                for (int j = 0; j < 8; j++)
                    acc[i][j] = fmaf(a[i], b[j], acc[i][j]);
        }
        if (s + 1 < NST) {
            float* An = As[(s+1) & 1];
            An[(akk+0)*128 + amm] = rA.x;
            An[(akk+1)*128 + amm] = rA.y;
            An[(akk+2)*128 + amm] = rA.z;
            An[(akk+3)*128 + amm] = rA.w;
            *(float4*)&Bs[(s+1) & 1][bkk*128 + bnn] = rB;
            __syncthreads();
        }
    }

    #pragma unroll
    for (int i = 0; i < 8; i++) {
        const int r = row0 + ty*8 + i;
        #pragma unroll
        for (int j = 0; j < 8; j += 4) {
            const int c = col0 + tx*8 + j;
            float4 o;
            o.x = acc[i][j+0] + bias[c+0];
            o.y = acc[i][j+1] + bias[c+1];
            o.z = acc[i][j+2] + bias[c+2];
            o.w = acc[i][j+3] + bias[c+3];
            *(float4*)&outp[(size_t)r*DIM + c] = o;
        }
    }
}

// ---------------------------------------------------------------------------
// top-32 insertion (local-memory sorted-descending lists)
// ---------------------------------------------------------------------------
__device__ __forceinline__ void insert_top(float* tv, int* ti, float s, int idx, float& thr)
{
    if (s > thr) {
        int p = TOPK - 1;
        while (p > 0 && tv[p-1] < s) {
            tv[p] = tv[p-1];
            ti[p] = ti[p-1];
            p--;
        }
        tv[p] = s;
        ti[p] = idx;
        thr = tv[TOPK-1];
    }
}

// ---------------------------------------------------------------------------
// Kernel 2: scores (pipelined fp32 GEMM) + per-chunk running top-32.
// grid = (128 bq-tiles, 4 key-chunks), 256 threads, 2 CTAs/SM.
// ---------------------------------------------------------------------------
__global__ __launch_bounds__(256, 2)
void score_kernel()
{
    extern __shared__ float sm[];
    float* As  = sm;                    // [2][BK][128]
    float* Bs  = As + 2*BK*128;         // [2][BK][128]
    float* Ssc = Bs + 2*BK*128;         // [128][SSTR]

    const int tid = threadIdx.x;
    const int tx = tid & 15, ty = tid >> 4;
    const int bq = blockIdx.x;
    const int chunk = blockIdx.y;
    const int b  = bq >> 5;
    const int qt = bq & 31;
    const int q0 = qt * TQ;
    const float* qb = g_q + (size_t)b*SEQ*DIM;
    const float* kb = g_k + (size_t)b*SEQ*DIM;

    // per-thread running top-32 (threads 0..127 own query q0+tid), local memory
    float tv[TOPK];
    int   ti[TOPK];
    #pragma unroll
    for (int j = 0; j < TOPK; j++) { tv[j] = -INFINITY; ti[j] = 0; }
    float thr = -INFINITY;

    const int amm = tid >> 1;
    const int akk = (tid & 1) * 4;

    const int NT   = CKEYS / TK;        // 8 key tiles
    const int NST  = NT * (DIM/BK);     // 256 flattened stages
    float4 rA, rB;

    // prologue: stage 0
    {
        const int kbase = chunk*CKEYS;
        rA = *(const float4*)&qb[(size_t)(q0 + amm)*DIM + akk];
        rB = *(const float4*)&kb[(size_t)(kbase + amm)*DIM + akk];
        As[(akk+0)*128 + amm] = rA.x;
        As[(akk+1)*128 + amm] = rA.y;
        As[(akk+2)*128 + amm] = rA.z;
        As[(akk+3)*128 + amm] = rA.w;
        Bs[(akk+0)*128 + amm] = rB.x;
        Bs[(akk+1)*128 + amm] = rB.y;
        Bs[(akk+2)*128 + amm] = rB.z;
        Bs[(akk+3)*128 + amm] = rB.w;
    }
    __syncthreads();

    for (int kt = 0; kt < NT; kt++) {
        const int kbase = chunk*CKEYS + kt*TK;

        float acc[8][8];
        #pragma unroll
        for (int i = 0; i < 8; i++)
            #pragma unroll
            for (int j = 0; j < 8; j++) acc[i][j] = 0.f;

        for (int k0i = 0; k0i < DIM/BK; k0i++) {
            const int s = kt*(DIM/BK) + k0i;
            if (s + 1 < NST) {
                const int sn = s + 1;
                const int ktn = sn >> 5;
                const int k0n = (sn & 31) * BK;
                const int kbn = chunk*CKEYS + ktn*TK;
                rA = *(const float4*)&qb[(size_t)(q0 + amm)*DIM + k0n + akk];
                rB = *(const float4*)&kb[(size_t)(kbn + amm)*DIM + k0n + akk];
            }
            const float* Ac = As + (s & 1)*BK*128;
            const float* Bc = Bs + (s & 1)*BK*128;
            #pragma unroll
            for (int kk = 0; kk < BK; kk++) {
                float a[8], bb[8];
                *(float4*)&a[0]  = *(const float4*)&Ac[kk*128 + ty*8];
                *(float4*)&a[4]  = *(const float4*)&Ac[kk*128 + ty*8 + 4];
                *(float4*)&bb[0] = *(const float4*)&Bc[kk*128 + tx*8];
                *(float4*)&bb[4] = *(const float4*)&Bc[kk*128 + tx*8 + 4];
                #pragma unroll
                for (int i = 0; i < 8; i++)
                    #pragma unroll
                    for (int j = 0; j < 8; j++)
                        acc[i][j] = fmaf(a[i], bb[j], acc[i][j]);
            }
            if (s + 1 < NST) {
                float* An = As + ((s+1) & 1)*BK*128;
                float* Bn = Bs + ((s+1) & 1)*BK*128;
                An[(akk+0)*128 + amm] = rA.x;
                An[(akk+1)*128 + amm] = rA.y;
                An[(akk+2)*128 + amm] = rA.z;
                An[(akk+3)*128 + amm] = rA.w;
                Bn[(akk+0)*128 + amm] = rB.x;
                Bn[(akk+1)*128 + amm] = rB.y;
                Bn[(akk+2)*128 + amm] = rB.z;
                Bn[(akk+3)*128 + amm] = rB.w;
            }
            __syncthreads();
        }

        // stage scores
        #pragma unroll
        for (int i = 0; i < 8; i++)
            #pragma unroll
            for (int j = 0; j < 8; j += 4)
                *(float4*)&Ssc[(ty*8 + i)*SSTR + tx*8 + j] = *(float4*)&acc[i][j];
        __syncthreads();

        // running top-32 scan (threads 0..127, float4)
        if (tid < TQ) {
            for (int j = 0; j < TK; j += 4) {
                float4 s4 = *(const float4*)&Ssc[tid*SSTR + j];
                insert_top(tv, ti, s4.x, kbase + j + 0, thr);
                insert_top(tv, ti, s4.y, kbase + j + 1, thr);
                insert_top(tv, ti, s4.z, kbase + j + 2, thr);
                insert_top(tv, ti, s4.w, kbase + j + 3, thr);
            }
        }
        __syncthreads();
    }

    // write partial sorted lists, [bq][chunk][j][q] (coalesced per j)
    if (tid < TQ) {
        const size_t base = ((size_t)bq*CHUNKS + chunk)*TOPK*128;
        #pragma unroll
        for (int j = 0; j < TOPK; j++) {
            g_pv[base + j*128 + tid] = tv[j];
            g_pi[base + j*128 + tid] = ti[j];
        }
    }
}

// ---------------------------------------------------------------------------
// Kernel 3: merge 4 sorted top-32 lists -> softmax -> AV gather.
// ---------------------------------------------------------------------------
#define TSTR 33
__global__ __launch_bounds__(256, 1)
void merge_kernel(float* __restrict__ out)
{
    extern __shared__ float sm[];
    float* mv   = sm;                              // [4][32][128]
    int*   mi   = (int*)(mv + CHUNKS*TOPK*128);
    float* pbuf = (float*)(mi + CHUNKS*TOPK*128);  // [128][TSTR]
    int*   ibuf = (int*)(pbuf + 128*TSTR);

    const int tid = threadIdx.x;
    const int bq = blockIdx.x;
    const int b  = bq >> 5;
    const int qt = bq & 31;
    const int q0 = qt * TQ;

    const size_t base = (size_t)bq*CHUNKS*TOPK*128;
    for (int i = tid; i < CHUNKS*TOPK*128; i += 256) {
        mv[i] = g_pv[base + i];
        mi[i] = g_pi[base + i];
    }
    __syncthreads();

    if (tid < TQ) {
        int p[CHUNKS] = {0,0,0,0};
        float m = 0.f, ssum = 0.f;
        for (int j = 0; j < TOPK; j++) {
            float best = -INFINITY;
            int bc = 0;
            #pragma unroll
            for (int c = 0; c < CHUNKS; c++) {
                float v = (p[c] < TOPK) ? mv[(c*TOPK + p[c])*128 + tid] : -INFINITY;
                if (v > best) { best = v; bc = c; }
            }
            int idx = mi[(bc*TOPK + p[bc])*128 + tid];
            p[bc]++;
            if (j == 0) m = best;
            float e = expf(best - m);
            pbuf[tid*TSTR + j] = e;
            ibuf[tid*TSTR + j] = idx;
            ssum += e;
        }
        float inv = 1.f / ssum;
        #pragma unroll
        for (int j = 0; j < TOPK; j++) pbuf[tid*TSTR + j] *= inv;
    }
    __syncthreads();

    // AV gather: thread owns dim column d = tid
    const float* vb = g_v + (size_t)b*SEQ*DIM;
    float* ob = out + ((size_t)b*SEQ + q0)*DIM;
    const int d = tid;
    for (int qq = 0; qq < TQ; qq++) {
        float accv = 0.f;
        #pragma unroll 8
        for (int j = 0; j < TOPK; j++) {
            float pp = pbuf[qq*TSTR + j];   // broadcast LDS
            int  idx = ibuf[qq*TSTR + j];
            accv = fmaf(pp, vb[(size_t)idx*DIM + d], accv);
        }
        ob[(size_t)qq*DIM + d] = accv;
    }
}

static const int SCORE_SMEM =
    (2*BK*128*2 + 128*SSTR) * (int)sizeof(float);                   // 83,968 B
static const int MERGE_SMEM =
    (CHUNKS*TOPK*128*2 + 128*TSTR*2) * (int)sizeof(float);          // 164,864 B

extern "C" void kernel_launch(void* const* d_in, const int* in_sizes, int n_in,
                              void* d_out, int out_size)
{
    const float* x  = (const float*)d_in[0];
    const float* Wq = (const float*)d_in[1];
    const float* bq = (const float*)d_in[2];
    const float* Wk = (const float*)d_in[3];
    const float* bk = (const float*)d_in[4];
    const float* Wv = (const float*)d_in[5];
    const float* bv = (const float*)d_in[6];
    float* out = (float*)d_out;

    cudaFuncSetAttribute(score_kernel,
                         cudaFuncAttributeMaxDynamicSharedMemorySize, SCORE_SMEM);
    cudaFuncSetAttribute(merge_kernel,
                         cudaFuncAttributeMaxDynamicSharedMemorySize, MERGE_SMEM);

    dim3 g1(ROWS/128, DIM/128, 3);
    qkv_kernel<<<g1, 256>>>(x, Wq, bq, Wk, bk, Wv, bv);

    dim3 g2(128, CHUNKS);
    score_kernel<<<g2, 256, SCORE_SMEM>>>();

    merge_kernel<<<128, 256, MERGE_SMEM>>>(out);
}

// round 7
// speedup vs baseline: 1.5893x; 1.5893x over previous
#include <cuda_runtime.h>
#include <math.h>
#include <stdint.h>

#define BATCH 4
#define SEQ   4096
#define DIM   256
#define TOPK  32
#define ROWS  (BATCH*SEQ)

#define TQ     128
#define TK     128
#define BK     8
#define SSTR   68    // score stage stride (floats), 64 keys + pad
#define TSTR   33    // top-list stride, conflict-free column access
#define CHUNKS 4
#define CKEYS  (SEQ/CHUNKS)   // 1024 keys per chunk CTA

typedef unsigned long long ull;

// ---------------- device scratch (allocation-free contract) ----------------
__device__ float g_qT[ROWS*DIM];   // [B][D][S] transposed
__device__ float g_kT[ROWS*DIM];   // [B][D][S] transposed
__device__ float g_v [ROWS*DIM];   // [B][S][D]
// partial top-k lists: [bq(128)][chunk(4)][j(32)][q(128)]
__device__ float g_pv[128*CHUNKS*TOPK*128];
__device__ int   g_pi[128*CHUNKS*TOPK*128];

// ---------------- f32x2 helpers ----------------
__device__ __forceinline__ ull pack2(float v) {
    ull r; uint32_t b = __float_as_uint(v);
    asm("mov.b64 %0, {%1, %1};" : "=l"(r) : "r"(b));
    return r;
}
__device__ __forceinline__ void fma2(ull& c, ull a, ull b) {
    asm("fma.rn.f32x2 %0, %1, %2, %3;" : "=l"(c) : "l"(a), "l"(b), "l"(c));
}
__device__ __forceinline__ float2 u2f(ull v) {
    float2 f;
    asm("mov.b64 {%0, %1}, %2;" : "=f"(f.x), "=f"(f.y) : "l"(v));
    return f;
}
__device__ __forceinline__ uint32_t smem_u32(const void* p) {
    uint32_t a;
    asm("{ .reg .u64 t; cvta.to.shared.u64 t, %1; cvt.u32.u64 %0, t; }" : "=r"(a) : "l"(p));
    return a;
}
__device__ __forceinline__ void cp_async16(uint32_t dst, const void* src) {
    asm volatile("cp.async.cg.shared.global [%0], [%1], 16;" :: "r"(dst), "l"(src));
}
#define CP_COMMIT() asm volatile("cp.async.commit_group;" ::: "memory")
#define CP_WAIT0()  asm volatile("cp.async.wait_group 0;" ::: "memory")

// ---------------------------------------------------------------------------
// Kernel 1: QKV projection, double-buffered pipeline, f32x2 FMA.
// q,k written transposed [B][D][S]; v written [B][S][D].
// ---------------------------------------------------------------------------
__global__ __launch_bounds__(256, 2)
void qkv_kernel(const float* __restrict__ x,
                const float* __restrict__ Wq, const float* __restrict__ bq,
                const float* __restrict__ Wk, const float* __restrict__ bk,
                const float* __restrict__ Wv, const float* __restrict__ bv)
{
    __shared__ float As[2][BK*128];
    __shared__ float Bs[2][BK*128];

    const int which = blockIdx.z;
    const float* W    = (which==0) ? Wq : (which==1) ? Wk : Wv;
    const float* bias = (which==0) ? bq : (which==1) ? bk : bv;

    const int tid = threadIdx.x;
    const int tx = tid & 15, ty = tid >> 4;
    const int row0 = blockIdx.x * 128;
    const int col0 = blockIdx.y * 128;

    ull acc[8][4];
    #pragma unroll
    for (int i = 0; i < 8; i++)
        #pragma unroll
        for (int j = 0; j < 4; j++) acc[i][j] = 0ull;

    const int amm = tid >> 1;
    const int akk = (tid & 1) * 4;
    const int bkk = tid >> 5;
    const int bnn = (tid & 31) * 4;

    const int NST = DIM / BK;   // 32 stages
    float4 rA, rB;

    rA = *(const float4*)&x[(size_t)(row0 + amm)*DIM + akk];
    rB = *(const float4*)&W[(size_t)bkk*DIM + col0 + bnn];
    As[0][(akk+0)*128 + amm] = rA.x;
    As[0][(akk+1)*128 + amm] = rA.y;
    As[0][(akk+2)*128 + amm] = rA.z;
    As[0][(akk+3)*128 + amm] = rA.w;
    *(float4*)&Bs[0][bkk*128 + bnn] = rB;
    __syncthreads();

    for (int s = 0; s < NST; s++) {
        if (s + 1 < NST) {
            const int k0 = (s+1) * BK;
            rA = *(const float4*)&x[(size_t)(row0 + amm)*DIM + k0 + akk];
            rB = *(const float4*)&W[(size_t)(k0 + bkk)*DIM + col0 + bnn];
        }
        const float* Ac = As[s & 1];
        const float* Bc = Bs[s & 1];
        #pragma unroll
        for (int kk = 0; kk < BK; kk++) {
            float a[8];
            *(float4*)&a[0] = *(const float4*)&Ac[kk*128 + ty*8];
            *(float4*)&a[4] = *(const float4*)&Ac[kk*128 + ty*8 + 4];
            ull b2[4];
            b2[0] = *(const ull*)&Bc[kk*128 + tx*8 + 0];
            b2[1] = *(const ull*)&Bc[kk*128 + tx*8 + 2];
            b2[2] = *(const ull*)&Bc[kk*128 + tx*8 + 4];
            b2[3] = *(const ull*)&Bc[kk*128 + tx*8 + 6];
            #pragma unroll
            for (int i = 0; i < 8; i++) {
                ull a2 = pack2(a[i]);
                #pragma unroll
                for (int j = 0; j < 4; j++) fma2(acc[i][j], a2, b2[j]);
            }
        }
        if (s + 1 < NST) {
            float* An = As[(s+1) & 1];
            An[(akk+0)*128 + amm] = rA.x;
            An[(akk+1)*128 + amm] = rA.y;
            An[(akk+2)*128 + amm] = rA.z;
            An[(akk+3)*128 + amm] = rA.w;
            *(float4*)&Bs[(s+1) & 1][bkk*128 + bnn] = rB;
            __syncthreads();
        }
    }

    if (which == 2) {
        // v: normal [row][dim] layout
        #pragma unroll
        for (int i = 0; i < 8; i++) {
            const int r = row0 + ty*8 + i;
            #pragma unroll
            for (int j2 = 0; j2 < 4; j2 += 2) {
                const int c = col0 + tx*8 + j2*2;
                float2 p0 = u2f(acc[i][j2]);
                float2 p1 = u2f(acc[i][j2+1]);
                float4 o;
                o.x = p0.x + bias[c+0];
                o.y = p0.y + bias[c+1];
                o.z = p1.x + bias[c+2];
                o.w = p1.y + bias[c+3];
                *(float4*)&g_v[(size_t)r*DIM + c] = o;
            }
        }
    } else {
        // q,k: transposed [B][D][S]; this CTA's rows lie in one batch
        float* outT = (which==0) ? g_qT : g_kT;
        const int bb = row0 >> 12;
        const int s0 = (row0 & (SEQ-1)) + ty*8;
        float* baseT = outT + (size_t)bb*DIM*SEQ;
        #pragma unroll
        for (int j = 0; j < 8; j++) {
            const int c = col0 + tx*8 + j;
            const float bc = bias[c];
            const int j2 = j >> 1;
            float v0, v1, v2, v3, v4, v5, v6, v7;
            if (j & 1) {
                v0 = u2f(acc[0][j2]).y; v1 = u2f(acc[1][j2]).y;
                v2 = u2f(acc[2][j2]).y; v3 = u2f(acc[3][j2]).y;
                v4 = u2f(acc[4][j2]).y; v5 = u2f(acc[5][j2]).y;
                v6 = u2f(acc[6][j2]).y; v7 = u2f(acc[7][j2]).y;
            } else {
                v0 = u2f(acc[0][j2]).x; v1 = u2f(acc[1][j2]).x;
                v2 = u2f(acc[2][j2]).x; v3 = u2f(acc[3][j2]).x;
                v4 = u2f(acc[4][j2]).x; v5 = u2f(acc[5][j2]).x;
                v6 = u2f(acc[6][j2]).x; v7 = u2f(acc[7][j2]).x;
            }
            float4 o0 = make_float4(v0+bc, v1+bc, v2+bc, v3+bc);
            float4 o1 = make_float4(v4+bc, v5+bc, v6+bc, v7+bc);
            *(float4*)&baseT[(size_t)c*SEQ + s0]     = o0;
            *(float4*)&baseT[(size_t)c*SEQ + s0 + 4] = o1;
        }
    }
}

// ---------------------------------------------------------------------------
// top-32 insertion into sorted-descending smem lists (stride TSTR)
// ---------------------------------------------------------------------------
__device__ __forceinline__ void insert_top(float* tv, int* ti, float s, int idx, float& thr)
{
    if (s > thr) {
        int p = TOPK - 1;
        while (p > 0 && tv[p-1] < s) {
            tv[p] = tv[p-1];
            ti[p] = ti[p-1];
            p--;
        }
        tv[p] = s;
        ti[p] = idx;
        thr = tv[TOPK-1];
    }
}

// ---------------------------------------------------------------------------
// Kernel 2: scores from transposed q/k, cp.async pipeline, f32x2 FMA,
// per-chunk running top-32 in SMEM. grid=(128,4), 256 thr, 2 CTAs/SM.
// ---------------------------------------------------------------------------
__global__ __launch_bounds__(256, 2)
void score_kernel()
{
    extern __shared__ float sm[];
    float* As   = sm;                        // [2][BK][128]
    float* Bs   = As + 2*BK*128;             // [2][BK][128]
    float* Ssc  = Bs + 2*BK*128;             // [128][SSTR] (64 keys/half)
    float* topV = Ssc + 128*SSTR;            // [128][TSTR]
    int*   topI = (int*)(topV + 128*TSTR);

    const uint32_t sAs = smem_u32(As);
    const uint32_t sBs = smem_u32(Bs);

    const int tid = threadIdx.x;
    const int tx = tid & 15, ty = tid >> 4;
    const int bq = blockIdx.x;
    const int chunk = blockIdx.y;
    const int b  = bq >> 5;
    const int qt = bq & 31;
    const int q0 = qt * TQ;
    const float* qb = g_qT + (size_t)b*DIM*SEQ;   // [D][S]
    const float* kb = g_kT + (size_t)b*DIM*SEQ;   // [D][S]

    for (int i = tid; i < 128*TSTR; i += 256) topV[i] = -INFINITY;

    // copy lane roles: kk = tid>>5 (0..7), c4 = (tid&31)*4
    const int ckk = tid >> 5;
    const int cc4 = (tid & 31) * 4;
    const uint32_t dA = (uint32_t)(ckk*128 + cc4) * 4u;
    const uint32_t dB = dA;

    const int NT  = CKEYS / TK;        // 8 key tiles
    const int NST = NT * (DIM/BK);     // 256 stages

    // prologue: stage 0
    cp_async16(sAs + dA, &qb[(size_t)ckk*SEQ + q0 + cc4]);
    cp_async16(sBs + dB, &kb[(size_t)ckk*SEQ + chunk*CKEYS + cc4]);
    CP_COMMIT();
    CP_WAIT0();
    __syncthreads();

    float thr = -INFINITY;
    float* tvp = topV + (tid & 127)*TSTR;
    int*   tip = topI + (tid & 127)*TSTR;

    for (int kt = 0; kt < NT; kt++) {
        const int kbase = chunk*CKEYS + kt*TK;

        ull acc[8][4];
        #pragma unroll
        for (int i = 0; i < 8; i++)
            #pragma unroll
            for (int j = 0; j < 4; j++) acc[i][j] = 0ull;

        for (int k0i = 0; k0i < DIM/BK; k0i++) {
            const int s = kt*(DIM/BK) + k0i;
            if (s + 1 < NST) {
                const int sn  = s + 1;
                const int ktn = sn >> 5;
                const int k0n = (sn & 31) * BK;
                const int kbn = chunk*CKEYS + ktn*TK;
                const uint32_t pb = (uint32_t)((sn & 1) * BK * 128) * 4u;
                cp_async16(sAs + pb + dA, &qb[(size_t)(k0n + ckk)*SEQ + q0 + cc4]);
                cp_async16(sBs + pb + dB, &kb[(size_t)(k0n + ckk)*SEQ + kbn + cc4]);
                CP_COMMIT();
            }
            const float* Ac = As + (s & 1)*BK*128;
            const float* Bc = Bs + (s & 1)*BK*128;
            #pragma unroll
            for (int kk = 0; kk < BK; kk++) {
                float a[8];
                *(float4*)&a[0] = *(const float4*)&Ac[kk*128 + ty*8];
                *(float4*)&a[4] = *(const float4*)&Ac[kk*128 + ty*8 + 4];
                ull b2[4];
                b2[0] = *(const ull*)&Bc[kk*128 + tx*8 + 0];
                b2[1] = *(const ull*)&Bc[kk*128 + tx*8 + 2];
                b2[2] = *(const ull*)&Bc[kk*128 + tx*8 + 4];
                b2[3] = *(const ull*)&Bc[kk*128 + tx*8 + 6];
                #pragma unroll
                for (int i = 0; i < 8; i++) {
                    ull a2 = pack2(a[i]);
                    #pragma unroll
                    for (int j = 0; j < 4; j++) fma2(acc[i][j], a2, b2[j]);
                }
            }
            CP_WAIT0();
            __syncthreads();
        }

        // stage + scan in two 64-key halves (half = tx>>3)
        #pragma unroll
        for (int half = 0; half < 2; half++) {
            if ((tx >> 3) == half) {
                const int cb = (tx & 7) * 8;
                #pragma unroll
                for (int i = 0; i < 8; i++) {
                    float* row = &Ssc[(ty*8 + i)*SSTR + cb];
                    #pragma unroll
                    for (int j2 = 0; j2 < 4; j2++)
                        *(float2*)&row[j2*2] = u2f(acc[i][j2]);
                }
            }
            __syncthreads();
            if (tid < TQ) {
                const int koff = kbase + half*64;
                for (int j = 0; j < 64; j += 4) {
                    float4 s4 = *(const float4*)&Ssc[tid*SSTR + j];
                    insert_top(tvp, tip, s4.x, koff + j + 0, thr);
                    insert_top(tvp, tip, s4.y, koff + j + 1, thr);
                    insert_top(tvp, tip, s4.z, koff + j + 2, thr);
                    insert_top(tvp, tip, s4.w, koff + j + 3, thr);
                }
            }
            __syncthreads();
        }
    }

    // write partial sorted lists, [bq][chunk][j][q] (coalesced per j)
    if (tid < TQ) {
        const size_t base = ((size_t)bq*CHUNKS + chunk)*TOPK*128;
        #pragma unroll
        for (int j = 0; j < TOPK; j++) {
            g_pv[base + j*128 + tid] = tvp[j];
            g_pi[base + j*128 + tid] = tip[j];
        }
    }
}

// ---------------------------------------------------------------------------
// Kernel 3: merge 4 sorted top-32 lists -> softmax -> AV gather.
// ---------------------------------------------------------------------------
__global__ __launch_bounds__(256, 1)
void merge_kernel(float* __restrict__ out)
{
    extern __shared__ float sm[];
    float* mv   = sm;                              // [4][32][128]
    int*   mi   = (int*)(mv + CHUNKS*TOPK*128);
    float* pbuf = (float*)(mi + CHUNKS*TOPK*128);  // [128][TSTR]
    int*   ibuf = (int*)(pbuf + 128*TSTR);

    const int tid = threadIdx.x;
    const int bq = blockIdx.x;
    const int b  = bq >> 5;
    const int qt = bq & 31;
    const int q0 = qt * TQ;

    const size_t base = (size_t)bq*CHUNKS*TOPK*128;
    for (int i = tid; i < CHUNKS*TOPK*128; i += 256) {
        mv[i] = g_pv[base + i];
        mi[i] = g_pi[base + i];
    }
    __syncthreads();

    if (tid < TQ) {
        int p[CHUNKS] = {0,0,0,0};
        float m = 0.f, ssum = 0.f;
        for (int j = 0; j < TOPK; j++) {
            float best = -INFINITY;
            int bc = 0;
            #pragma unroll
            for (int c = 0; c < CHUNKS; c++) {
                float v = (p[c] < TOPK) ? mv[(c*TOPK + p[c])*128 + tid] : -INFINITY;
                if (v > best) { best = v; bc = c; }
            }
            int idx = mi[(bc*TOPK + p[bc])*128 + tid];
            p[bc]++;
            if (j == 0) m = best;
            float e = expf(best - m);
            pbuf[tid*TSTR + j] = e;
            ibuf[tid*TSTR + j] = idx;
            ssum += e;
        }
        float inv = 1.f / ssum;
        #pragma unroll
        for (int j = 0; j < TOPK; j++) pbuf[tid*TSTR + j] *= inv;
    }
    __syncthreads();

    // AV gather: thread owns dim column d = tid
    const float* vb = g_v + (size_t)b*SEQ*DIM;
    float* ob = out + ((size_t)b*SEQ + q0)*DIM;
    const int d = tid;
    for (int qq = 0; qq < TQ; qq++) {
        float accv = 0.f;
        #pragma unroll 8
        for (int j = 0; j < TOPK; j++) {
            float pp = pbuf[qq*TSTR + j];   // broadcast LDS
            int  idx = ibuf[qq*TSTR + j];
            accv = fmaf(pp, vb[(size_t)idx*DIM + d], accv);
        }
        ob[(size_t)qq*DIM + d] = accv;
    }
}

static const int SCORE_SMEM =
    (2*BK*128*2 + 128*SSTR + 128*TSTR) * (int)sizeof(float)
    + 128*TSTR*(int)sizeof(int);                                    // 85,504 B
static const int MERGE_SMEM =
    (CHUNKS*TOPK*128*2 + 128*TSTR*2) * (int)sizeof(float);          // 164,864 B

extern "C" void kernel_launch(void* const* d_in, const int* in_sizes, int n_in,
                              void* d_out, int out_size)
{
    const float* x  = (const float*)d_in[0];
    const float* Wq = (const float*)d_in[1];
    const float* bq = (const float*)d_in[2];
    const float* Wk = (const float*)d_in[3];
    const float* bk = (const float*)d_in[4];
    const float* Wv = (const float*)d_in[5];
    const float* bv = (const float*)d_in[6];
    float* out = (float*)d_out;

    cudaFuncSetAttribute(score_kernel,
                         cudaFuncAttributeMaxDynamicSharedMemorySize, SCORE_SMEM);
    cudaFuncSetAttribute(merge_kernel,
                         cudaFuncAttributeMaxDynamicSharedMemorySize, MERGE_SMEM);

    dim3 g1(ROWS/128, DIM/128, 3);
    qkv_kernel<<<g1, 256>>>(x, Wq, bq, Wk, bk, Wv, bv);

    dim3 g2(128, CHUNKS);
    score_kernel<<<g2, 256, SCORE_SMEM>>>();

    merge_kernel<<<128, 256, MERGE_SMEM>>>(out);
}

// round 8
// speedup vs baseline: 2.3319x; 1.4672x over previous
#include <cuda_runtime.h>
#include <math.h>
#include <stdint.h>

#define BATCH 4
#define SEQ   4096
#define DIM   256
#define TOPK  32
#define ROWS  (BATCH*SEQ)

#define TQ     128
#define TK     128
#define BK     8
#define SSTR   68    // score stage stride (floats): 64 keys + pad
#define TSTR   33    // top-list stride, conflict-free column access
#define CHUNKS 4
#define CKEYS  (SEQ/CHUNKS)   // 1024 keys per chunk CTA

// ---------------- device scratch (allocation-free contract) ----------------
__device__ float g_q[ROWS*DIM];
__device__ float g_k[ROWS*DIM];
__device__ float g_v[ROWS*DIM];
// partial top-k lists: [bq(128)][chunk(4)][j(32)][q(128)]
__device__ float g_pv[128*CHUNKS*TOPK*128];
__device__ int   g_pi[128*CHUNKS*TOPK*128];

// ---------------------------------------------------------------------------
// Kernel 1: fused QKV projection, double-buffered pipeline, scalar FMA.
// (R6-validated: 165 us, issue 66.5%)
// ---------------------------------------------------------------------------
__global__ __launch_bounds__(256, 2)
void qkv_kernel(const float* __restrict__ x,
                const float* __restrict__ Wq, const float* __restrict__ bq,
                const float* __restrict__ Wk, const float* __restrict__ bk,
                const float* __restrict__ Wv, const float* __restrict__ bv)
{
    __shared__ float As[2][BK*128];
    __shared__ float Bs[2][BK*128];

    const int which = blockIdx.z;
    const float* W    = (which==0) ? Wq : (which==1) ? Wk : Wv;
    const float* bias = (which==0) ? bq : (which==1) ? bk : bv;
    float* outp       = (which==0) ? g_q : (which==1) ? g_k : g_v;

    const int tid = threadIdx.x;
    const int tx = tid & 15, ty = tid >> 4;
    const int row0 = blockIdx.x * 128;
    const int col0 = blockIdx.y * 128;

    float acc[8][8];
    #pragma unroll
    for (int i = 0; i < 8; i++)
        #pragma unroll
        for (int j = 0; j < 8; j++) acc[i][j] = 0.f;

    const int amm = tid >> 1;
    const int akk = (tid & 1) * 4;
    const int bkk = tid >> 5;
    const int bnn = (tid & 31) * 4;

    const int NST = DIM / BK;   // 32 stages
    float4 rA, rB;

    rA = *(const float4*)&x[(size_t)(row0 + amm)*DIM + akk];
    rB = *(const float4*)&W[(size_t)bkk*DIM + col0 + bnn];
    As[0][(akk+0)*128 + amm] = rA.x;
    As[0][(akk+1)*128 + amm] = rA.y;
    As[0][(akk+2)*128 + amm] = rA.z;
    As[0][(akk+3)*128 + amm] = rA.w;
    *(float4*)&Bs[0][bkk*128 + bnn] = rB;
    __syncthreads();

    for (int s = 0; s < NST; s++) {
        if (s + 1 < NST) {
            const int k0 = (s+1) * BK;
            rA = *(const float4*)&x[(size_t)(row0 + amm)*DIM + k0 + akk];
            rB = *(const float4*)&W[(size_t)(k0 + bkk)*DIM + col0 + bnn];
        }
        const float* Ac = As[s & 1];
        const float* Bc = Bs[s & 1];
        #pragma unroll
        for (int kk = 0; kk < BK; kk++) {
            float a[8], b[8];
            *(float4*)&a[0] = *(const float4*)&Ac[kk*128 + ty*8];
            *(float4*)&a[4] = *(const float4*)&Ac[kk*128 + ty*8 + 4];
            *(float4*)&b[0] = *(const float4*)&Bc[kk*128 + tx*8];
            *(float4*)&b[4] = *(const float4*)&Bc[kk*128 + tx*8 + 4];
            #pragma unroll
            for (int i = 0; i < 8; i++)
                #pragma unroll
                for (int j = 0; j < 8; j++)
                    acc[i][j] = fmaf(a[i], b[j], acc[i][j]);
        }
        if (s + 1 < NST) {
            float* An = As[(s+1) & 1];
            An[(akk+0)*128 + amm] = rA.x;
            An[(akk+1)*128 + amm] = rA.y;
            An[(akk+2)*128 + amm] = rA.z;
            An[(akk+3)*128 + amm] = rA.w;
            *(float4*)&Bs[(s+1) & 1][bkk*128 + bnn] = rB;
            __syncthreads();
        }
    }

    #pragma unroll
    for (int i = 0; i < 8; i++) {
        const int r = row0 + ty*8 + i;
        #pragma unroll
        for (int j = 0; j < 8; j += 4) {
            const int c = col0 + tx*8 + j;
            float4 o;
            o.x = acc[i][j+0] + bias[c+0];
            o.y = acc[i][j+1] + bias[c+1];
            o.z = acc[i][j+2] + bias[c+2];
            o.w = acc[i][j+3] + bias[c+3];
            *(float4*)&outp[(size_t)r*DIM + c] = o;
        }
    }
}

// ---------------------------------------------------------------------------
// top-32 insertion into sorted-descending smem lists (stride TSTR)
// ---------------------------------------------------------------------------
__device__ __forceinline__ void insert_top(float* tv, int* ti, float s, int idx, float& thr)
{
    if (s > thr) {
        int p = TOPK - 1;
        while (p > 0 && tv[p-1] < s) {
            tv[p] = tv[p-1];
            ti[p] = ti[p-1];
            p--;
        }
        tv[p] = s;
        ti[p] = idx;
        thr = tv[TOPK-1];
    }
}

// ---------------------------------------------------------------------------
// Kernel 2: scores (pipelined scalar fp32 GEMM) + per-chunk running top-32
// in SMEM. grid = (128 bq-tiles, 4 key-chunks), 256 threads, 2 CTAs/SM.
// ---------------------------------------------------------------------------
__global__ __launch_bounds__(256, 2)
void score_kernel()
{
    extern __shared__ float sm[];
    float* As   = sm;                        // [2][BK][128]
    float* Bs   = As + 2*BK*128;             // [2][BK][128]
    float* Ssc  = Bs + 2*BK*128;             // [128][SSTR] (64 keys per half)
    float* topV = Ssc + 128*SSTR;            // [128][TSTR]
    int*   topI = (int*)(topV + 128*TSTR);

    const int tid = threadIdx.x;
    const int tx = tid & 15, ty = tid >> 4;
    const int bq = blockIdx.x;
    const int chunk = blockIdx.y;
    const int b  = bq >> 5;
    const int qt = bq & 31;
    const int q0 = qt * TQ;
    const float* qb = g_q + (size_t)b*SEQ*DIM;
    const float* kb = g_k + (size_t)b*SEQ*DIM;

    for (int i = tid; i < 128*TSTR; i += 256) topV[i] = -INFINITY;

    const int amm = tid >> 1;
    const int akk = (tid & 1) * 4;

    const int NT  = CKEYS / TK;        // 8 key tiles
    const int NST = NT * (DIM/BK);     // 256 flattened stages
    float4 rA, rB;

    // prologue: stage 0
    rA = *(const float4*)&qb[(size_t)(q0 + amm)*DIM + akk];
    rB = *(const float4*)&kb[(size_t)(chunk*CKEYS + amm)*DIM + akk];
    As[(akk+0)*128 + amm] = rA.x;
    As[(akk+1)*128 + amm] = rA.y;
    As[(akk+2)*128 + amm] = rA.z;
    As[(akk+3)*128 + amm] = rA.w;
    Bs[(akk+0)*128 + amm] = rB.x;
    Bs[(akk+1)*128 + amm] = rB.y;
    Bs[(akk+2)*128 + amm] = rB.z;
    Bs[(akk+3)*128 + amm] = rB.w;
    __syncthreads();

    float thr = -INFINITY;
    float* tvp = topV + (tid & 127)*TSTR;
    int*   tip = topI + (tid & 127)*TSTR;

    for (int kt = 0; kt < NT; kt++) {
        const int kbase = chunk*CKEYS + kt*TK;

        float acc[8][8];
        #pragma unroll
        for (int i = 0; i < 8; i++)
            #pragma unroll
            for (int j = 0; j < 8; j++) acc[i][j] = 0.f;

        for (int k0i = 0; k0i < DIM/BK; k0i++) {
            const int s = kt*(DIM/BK) + k0i;
            if (s + 1 < NST) {
                const int sn  = s + 1;
                const int ktn = sn >> 5;
                const int k0n = (sn & 31) * BK;
                const int kbn = chunk*CKEYS + ktn*TK;
                rA = *(const float4*)&qb[(size_t)(q0 + amm)*DIM + k0n + akk];
                rB = *(const float4*)&kb[(size_t)(kbn + amm)*DIM + k0n + akk];
            }
            const float* Ac = As + (s & 1)*BK*128;
            const float* Bc = Bs + (s & 1)*BK*128;
            #pragma unroll
            for (int kk = 0; kk < BK; kk++) {
                float a[8], bb[8];
                *(float4*)&a[0]  = *(const float4*)&Ac[kk*128 + ty*8];
                *(float4*)&a[4]  = *(const float4*)&Ac[kk*128 + ty*8 + 4];
                *(float4*)&bb[0] = *(const float4*)&Bc[kk*128 + tx*8];
                *(float4*)&bb[4] = *(const float4*)&Bc[kk*128 + tx*8 + 4];
                #pragma unroll
                for (int i = 0; i < 8; i++)
                    #pragma unroll
                    for (int j = 0; j < 8; j++)
                        acc[i][j] = fmaf(a[i], bb[j], acc[i][j]);
            }
            if (s + 1 < NST) {
                float* An = As + ((s+1) & 1)*BK*128;
                float* Bn = Bs + ((s+1) & 1)*BK*128;
                An[(akk+0)*128 + amm] = rA.x;
                An[(akk+1)*128 + amm] = rA.y;
                An[(akk+2)*128 + amm] = rA.z;
                An[(akk+3)*128 + amm] = rA.w;
                Bn[(akk+0)*128 + amm] = rB.x;
                Bn[(akk+1)*128 + amm] = rB.y;
                Bn[(akk+2)*128 + amm] = rB.z;
                Bn[(akk+3)*128 + amm] = rB.w;
            }
            __syncthreads();
        }

        // stage + scan in two 64-key halves (warps with tx>>3 == half stage)
        #pragma unroll
        for (int half = 0; half < 2; half++) {
            if ((tx >> 3) == half) {
                const int cb = (tx & 7) * 8;
                #pragma unroll
                for (int i = 0; i < 8; i++) {
                    float* row = &Ssc[(ty*8 + i)*SSTR + cb];
                    #pragma unroll
                    for (int j = 0; j < 8; j += 4)
                        *(float4*)&row[j] = *(float4*)&acc[i][j];
                }
            }
            __syncthreads();
            if (tid < TQ) {
                const int koff = kbase + half*64;
                for (int j = 0; j < 64; j += 4) {
                    float4 s4 = *(const float4*)&Ssc[tid*SSTR + j];
                    insert_top(tvp, tip, s4.x, koff + j + 0, thr);
                    insert_top(tvp, tip, s4.y, koff + j + 1, thr);
                    insert_top(tvp, tip, s4.z, koff + j + 2, thr);
                    insert_top(tvp, tip, s4.w, koff + j + 3, thr);
                }
            }
            __syncthreads();
        }
    }

    // write partial sorted lists, [bq][chunk][j][q] (coalesced per j)
    if (tid < TQ) {
        const size_t base = ((size_t)bq*CHUNKS + chunk)*TOPK*128;
        #pragma unroll
        for (int j = 0; j < TOPK; j++) {
            g_pv[base + j*128 + tid] = tvp[j];
            g_pi[base + j*128 + tid] = tip[j];
        }
    }
}

// ---------------------------------------------------------------------------
// Kernel 3: merge 4 sorted top-32 lists -> softmax -> AV gather.
// ---------------------------------------------------------------------------
__global__ __launch_bounds__(256, 1)
void merge_kernel(float* __restrict__ out)
{
    extern __shared__ float sm[];
    float* mv   = sm;                              // [4][32][128]
    int*   mi   = (int*)(mv + CHUNKS*TOPK*128);
    float* pbuf = (float*)(mi + CHUNKS*TOPK*128);  // [128][TSTR]
    int*   ibuf = (int*)(pbuf + 128*TSTR);

    const int tid = threadIdx.x;
    const int bq = blockIdx.x;
    const int b  = bq >> 5;
    const int qt = bq & 31;
    const int q0 = qt * TQ;

    const size_t base = (size_t)bq*CHUNKS*TOPK*128;
    for (int i = tid; i < CHUNKS*TOPK*128; i += 256) {
        mv[i] = g_pv[base + i];
        mi[i] = g_pi[base + i];
    }
    __syncthreads();

    if (tid < TQ) {
        int p[CHUNKS] = {0,0,0,0};
        float m = 0.f, ssum = 0.f;
        for (int j = 0; j < TOPK; j++) {
            float best = -INFINITY;
            int bc = 0;
            #pragma unroll
            for (int c = 0; c < CHUNKS; c++) {
                float v = (p[c] < TOPK) ? mv[(c*TOPK + p[c])*128 + tid] : -INFINITY;
                if (v > best) { best = v; bc = c; }
            }
            int idx = mi[(bc*TOPK + p[bc])*128 + tid];
            p[bc]++;
            if (j == 0) m = best;
            float e = expf(best - m);
            pbuf[tid*TSTR + j] = e;
            ibuf[tid*TSTR + j] = idx;
            ssum += e;
        }
        float inv = 1.f / ssum;
        #pragma unroll
        for (int j = 0; j < TOPK; j++) pbuf[tid*TSTR + j] *= inv;
    }
    __syncthreads();

    // AV gather: thread owns dim column d = tid
    const float* vb = g_v + (size_t)b*SEQ*DIM;
    float* ob = out + ((size_t)b*SEQ + q0)*DIM;
    const int d = tid;
    for (int qq = 0; qq < TQ; qq++) {
        float accv = 0.f;
        #pragma unroll 8
        for (int j = 0; j < TOPK; j++) {
            float pp = pbuf[qq*TSTR + j];   // broadcast LDS
            int  idx = ibuf[qq*TSTR + j];
            accv = fmaf(pp, vb[(size_t)idx*DIM + d], accv);
        }
        ob[(size_t)qq*DIM + d] = accv;
    }
}

static const int SCORE_SMEM =
    (2*BK*128*2 + 128*SSTR + 128*TSTR) * (int)sizeof(float)
    + 128*TSTR*(int)sizeof(int);                                    // 85,504 B
static const int MERGE_SMEM =
    (CHUNKS*TOPK*128*2 + 128*TSTR*2) * (int)sizeof(float);          // 164,864 B

extern "C" void kernel_launch(void* const* d_in, const int* in_sizes, int n_in,
                              void* d_out, int out_size)
{
    const float* x  = (const float*)d_in[0];
    const float* Wq = (const float*)d_in[1];
    const float* bq = (const float*)d_in[2];
    const float* Wk = (const float*)d_in[3];
    const float* bk = (const float*)d_in[4];
    const float* Wv = (const float*)d_in[5];
    const float* bv = (const float*)d_in[6];
    float* out = (float*)d_out;

    cudaFuncSetAttribute(score_kernel,
                         cudaFuncAttributeMaxDynamicSharedMemorySize, SCORE_SMEM);
    cudaFuncSetAttribute(merge_kernel,
                         cudaFuncAttributeMaxDynamicSharedMemorySize, MERGE_SMEM);

    dim3 g1(ROWS/128, DIM/128, 3);
    qkv_kernel<<<g1, 256>>>(x, Wq, bq, Wk, bk, Wv, bv);

    dim3 g2(128, CHUNKS);
    score_kernel<<<g2, 256, SCORE_SMEM>>>();

    merge_kernel<<<128, 256, MERGE_SMEM>>>(out);
}

// round 10
// speedup vs baseline: 5.2022x; 2.2309x over previous
#include <cuda_runtime.h>
#include <math.h>
#include <stdint.h>

#define BATCH 4
#define SEQ   4096
#define DIM   256
#define TOPK  32
#define ROWS  (BATCH*SEQ)
#define BK    8

#define FULLM 0xffffffffu

// ---------------- device scratch (allocation-free contract) ----------------
__device__ float g_q[ROWS*DIM];
__device__ float g_k[ROWS*DIM];
__device__ float g_v[ROWS*DIM];
__device__ float g_s[(size_t)BATCH*SEQ*SEQ];   // 268 MB score matrix

// ---------------------------------------------------------------------------
// Kernel 1: fused QKV projection, double-buffered pipeline (R8-validated).
// ---------------------------------------------------------------------------
__global__ __launch_bounds__(256, 2)
void qkv_kernel(const float* __restrict__ x,
                const float* __restrict__ Wq, const float* __restrict__ bq,
                const float* __restrict__ Wk, const float* __restrict__ bk,
                const float* __restrict__ Wv, const float* __restrict__ bv)
{
    __shared__ float As[2][BK*128];
    __shared__ float Bs[2][BK*128];

    const int which = blockIdx.z;
    const float* W    = (which==0) ? Wq : (which==1) ? Wk : Wv;
    const float* bias = (which==0) ? bq : (which==1) ? bk : bv;
    float* outp       = (which==0) ? g_q : (which==1) ? g_k : g_v;

    const int tid = threadIdx.x;
    const int tx = tid & 15, ty = tid >> 4;
    const int row0 = blockIdx.x * 128;
    const int col0 = blockIdx.y * 128;

    float acc[8][8];
    #pragma unroll
    for (int i = 0; i < 8; i++)
        #pragma unroll
        for (int j = 0; j < 8; j++) acc[i][j] = 0.f;

    const int amm = tid >> 1;
    const int akk = (tid & 1) * 4;
    const int bkk = tid >> 5;
    const int bnn = (tid & 31) * 4;

    const int NST = DIM / BK;   // 32 stages
    float4 rA, rB;

    rA = *(const float4*)&x[(size_t)(row0 + amm)*DIM + akk];
    rB = *(const float4*)&W[(size_t)bkk*DIM + col0 + bnn];
    As[0][(akk+0)*128 + amm] = rA.x;
    As[0][(akk+1)*128 + amm] = rA.y;
    As[0][(akk+2)*128 + amm] = rA.z;
    As[0][(akk+3)*128 + amm] = rA.w;
    *(float4*)&Bs[0][bkk*128 + bnn] = rB;
    __syncthreads();

    for (int s = 0; s < NST; s++) {
        if (s + 1 < NST) {
            const int k0 = (s+1) * BK;
            rA = *(const float4*)&x[(size_t)(row0 + amm)*DIM + k0 + akk];
            rB = *(const float4*)&W[(size_t)(k0 + bkk)*DIM + col0 + bnn];
        }
        const float* Ac = As[s & 1];
        const float* Bc = Bs[s & 1];
        #pragma unroll
        for (int kk = 0; kk < BK; kk++) {
            float a[8], b[8];
            *(float4*)&a[0] = *(const float4*)&Ac[kk*128 + ty*8];
            *(float4*)&a[4] = *(const float4*)&Ac[kk*128 + ty*8 + 4];
            *(float4*)&b[0] = *(const float4*)&Bc[kk*128 + tx*8];
            *(float4*)&b[4] = *(const float4*)&Bc[kk*128 + tx*8 + 4];
            #pragma unroll
            for (int i = 0; i < 8; i++)
                #pragma unroll
                for (int j = 0; j < 8; j++)
                    acc[i][j] = fmaf(a[i], b[j], acc[i][j]);
        }
        if (s + 1 < NST) {
            float* An = As[(s+1) & 1];
            An[(akk+0)*128 + amm] = rA.x;
            An[(akk+1)*128 + amm] = rA.y;
            An[(akk+2)*128 + amm] = rA.z;
            An[(akk+3)*128 + amm] = rA.w;
            *(float4*)&Bs[(s+1) & 1][bkk*128 + bnn] = rB;
            __syncthreads();
        }
    }

    #pragma unroll
    for (int i = 0; i < 8; i++) {
        const int r = row0 + ty*8 + i;
        #pragma unroll
        for (int j = 0; j < 8; j += 4) {
            const int c = col0 + tx*8 + j;
            float4 o;
            o.x = acc[i][j+0] + bias[c+0];
            o.y = acc[i][j+1] + bias[c+1];
            o.z = acc[i][j+2] + bias[c+2];
            o.w = acc[i][j+3] + bias[c+3];
            *(float4*)&outp[(size_t)r*DIM + c] = o;
        }
    }
}

// ---------------------------------------------------------------------------
// Kernel 2: pure score GEMM  S[b][q][k] = q_row . k_row, pipelined.
// grid = (32 k-tiles, 32 q-tiles, 4 batches), 256 threads, 2 CTAs/SM.
// ---------------------------------------------------------------------------
__global__ __launch_bounds__(256, 2)
void sgemm_kernel()
{
    __shared__ float As[2][BK*128];
    __shared__ float Bs[2][BK*128];

    const int tid = threadIdx.x;
    const int tx = tid & 15, ty = tid >> 4;
    const int k0t = blockIdx.x * 128;
    const int q0t = blockIdx.y * 128;
    const int b   = blockIdx.z;
    const float* qb = g_q + (size_t)b*SEQ*DIM;
    const float* kb = g_k + (size_t)b*SEQ*DIM;

    float acc[8][8];
    #pragma unroll
    for (int i = 0; i < 8; i++)
        #pragma unroll
        for (int j = 0; j < 8; j++) acc[i][j] = 0.f;

    const int amm = tid >> 1;
    const int akk = (tid & 1) * 4;

    const int NST = DIM / BK;   // 32 stages
    float4 rA, rB;

    rA = *(const float4*)&qb[(size_t)(q0t + amm)*DIM + akk];
    rB = *(const float4*)&kb[(size_t)(k0t + amm)*DIM + akk];
    As[0][(akk+0)*128 + amm] = rA.x;
    As[0][(akk+1)*128 + amm] = rA.y;
    As[0][(akk+2)*128 + amm] = rA.z;
    As[0][(akk+3)*128 + amm] = rA.w;
    Bs[0][(akk+0)*128 + amm] = rB.x;
    Bs[0][(akk+1)*128 + amm] = rB.y;
    Bs[0][(akk+2)*128 + amm] = rB.z;
    Bs[0][(akk+3)*128 + amm] = rB.w;
    __syncthreads();

    for (int s = 0; s < NST; s++) {
        if (s + 1 < NST) {
            const int kd = (s+1) * BK;
            rA = *(const float4*)&qb[(size_t)(q0t + amm)*DIM + kd + akk];
            rB = *(const float4*)&kb[(size_t)(k0t + amm)*DIM + kd + akk];
        }
        const float* Ac = As[s & 1];
        const float* Bc = Bs[s & 1];
        #pragma unroll
        for (int kk = 0; kk < BK; kk++) {
            float a[8], bb[8];
            *(float4*)&a[0]  = *(const float4*)&Ac[kk*128 + ty*8];
            *(float4*)&a[4]  = *(const float4*)&Ac[kk*128 + ty*8 + 4];
            *(float4*)&bb[0] = *(const float4*)&Bc[kk*128 + tx*8];
            *(float4*)&bb[4] = *(const float4*)&Bc[kk*128 + tx*8 + 4];
            #pragma unroll
            for (int i = 0; i < 8; i++)
                #pragma unroll
                for (int j = 0; j < 8; j++)
                    acc[i][j] = fmaf(a[i], bb[j], acc[i][j]);
        }
        if (s + 1 < NST) {
            float* An = As[(s+1) & 1];
            float* Bn = Bs[(s+1) & 1];
            An[(akk+0)*128 + amm] = rA.x;
            An[(akk+1)*128 + amm] = rA.y;
            An[(akk+2)*128 + amm] = rA.z;
            An[(akk+3)*128 + amm] = rA.w;
            Bn[(akk+0)*128 + amm] = rB.x;
            Bn[(akk+1)*128 + amm] = rB.y;
            Bn[(akk+2)*128 + amm] = rB.z;
            Bn[(akk+3)*128 + amm] = rB.w;
            __syncthreads();
        }
    }

    // store S tile
    float* srow = g_s + ((size_t)b*SEQ + q0t)*SEQ + k0t;
    #pragma unroll
    for (int i = 0; i < 8; i++) {
        float* r = srow + (size_t)(ty*8 + i)*SEQ + tx*8;
        #pragma unroll
        for (int j = 0; j < 8; j += 4)
            *(float4*)&r[j] = *(float4*)&acc[i][j];
    }
}

// ---------------------------------------------------------------------------
// Kernel 3: warp-per-query top-32 (register-resident, shfl shift-insert)
// + softmax + AV gather. grid = 2048 CTAs x 256 threads (8 warps/CTA).
// ---------------------------------------------------------------------------
__global__ __launch_bounds__(256)
void select_kernel(float* __restrict__ out)
{
    const int lane = threadIdx.x & 31;
    const int gq   = blockIdx.x * 8 + (threadIdx.x >> 5);   // global query id
    const int b    = gq >> 12;
    const int q    = gq & (SEQ-1);

    float myval = -INFINITY;   // rank-`lane` value (descending across lanes)
    int   myidx = 0;

    const float4* srow = (const float4*)(g_s + ((size_t)b*SEQ + q)*SEQ);

    #pragma unroll 1
    for (int i = 0; i < SEQ/128; i++) {
        float4 s4 = srow[i*32 + lane];
        float thr = __shfl_sync(FULLM, myval, 31);
        bool cand = (s4.x > thr) | (s4.y > thr) | (s4.z > thr) | (s4.w > thr);
        if (__any_sync(FULLM, cand)) {
            #pragma unroll
            for (int t = 0; t < 4; t++) {
                float v = (t==0) ? s4.x : (t==1) ? s4.y : (t==2) ? s4.z : s4.w;
                thr = __shfl_sync(FULLM, myval, 31);
                unsigned cm = __ballot_sync(FULLM, v > thr);
                while (cm) {
                    int src = __ffs(cm) - 1;
                    cm &= cm - 1;
                    float bv  = __shfl_sync(FULLM, v, src);
                    int  bidx = i*128 + src*4 + t;
                    bool gt = bv > myval;
                    unsigned bm = __ballot_sync(FULLM, gt);
                    float upv = __shfl_up_sync(FULLM, myval, 1);
                    int   upi = __shfl_up_sync(FULLM, myidx, 1);
                    if (bm) {
                        int p = __ffs(bm) - 1;
                        if (gt) {
                            myval = (lane == p) ? bv : upv;
                            myidx = (lane == p) ? bidx : upi;
                        }
                    }
                }
            }
        }
    }

    // softmax over the 32 kept values (lane 0 holds the max)
    float mx = __shfl_sync(FULLM, myval, 0);
    float e  = expf(myval - mx);
    float ssum = e;
    #pragma unroll
    for (int o = 16; o; o >>= 1) ssum += __shfl_xor_sync(FULLM, ssum, o);
    float p = e / ssum;

    // AV gather: lane covers dims [lane*8, lane*8+8)
    const float4* vb = (const float4*)(g_v + (size_t)b*SEQ*DIM);
    float4 a0 = make_float4(0.f,0.f,0.f,0.f);
    float4 a1 = make_float4(0.f,0.f,0.f,0.f);
    #pragma unroll 4
    for (int j = 0; j < TOPK; j++) {
        float pj = __shfl_sync(FULLM, p, j);
        int   ij = __shfl_sync(FULLM, myidx, j);
        float4 v0 = vb[(size_t)ij*64 + lane*2];
        float4 v1 = vb[(size_t)ij*64 + lane*2 + 1];
        a0.x = fmaf(pj, v0.x, a0.x);
        a0.y = fmaf(pj, v0.y, a0.y);
        a0.z = fmaf(pj, v0.z, a0.z);
        a0.w = fmaf(pj, v0.w, a0.w);
        a1.x = fmaf(pj, v1.x, a1.x);
        a1.y = fmaf(pj, v1.y, a1.y);
        a1.z = fmaf(pj, v1.z, a1.z);
        a1.w = fmaf(pj, v1.w, a1.w);
    }
    float4* ob = (float4*)(out + ((size_t)b*SEQ + q)*DIM);
    ob[lane*2]     = a0;
    ob[lane*2 + 1] = a1;
}

extern "C" void kernel_launch(void* const* d_in, const int* in_sizes, int n_in,
                              void* d_out, int out_size)
{
    const float* x  = (const float*)d_in[0];
    const float* Wq = (const float*)d_in[1];
    const float* bq = (const float*)d_in[2];
    const float* Wk = (const float*)d_in[3];
    const float* bk = (const float*)d_in[4];
    const float* Wv = (const float*)d_in[5];
    const float* bv = (const float*)d_in[6];
    float* out = (float*)d_out;

    dim3 g1(ROWS/128, DIM/128, 3);
    qkv_kernel<<<g1, 256>>>(x, Wq, bq, Wk, bk, Wv, bv);

    dim3 g2(SEQ/128, SEQ/128, BATCH);
    sgemm_kernel<<<g2, 256>>>();

    select_kernel<<<(BATCH*SEQ)/8, 256>>>(out);
}